// round 12
// baseline (speedup 1.0000x reference)
#include <cuda_runtime.h>
#include <math.h>
#include <stdint.h>

#define SUB_NO 20
#define T_NO   201
#define E_NO   2000
#define I_NO   500
#define NSYN   2500
#define T_DATA 20000
#define NCH    60
#define CTT    512
#define OFFS   208

#define NCHUNK_E 63
#define NCHUNK_I 16
#define NCHUNKS  (NCHUNK_E + NCHUNK_I)
#define KSLOTS   (NCHUNKS * 32)     // 2528

// output layout (floats)
#define OFF_THETA 60000
#define OFF_HARD  110000
#define OFF_SOFT  160000
#define OFF_ZB    210000

// scratch
__device__ float g_in[2][NCH][T_DATA];
__device__ float g_syn[NCH][T_DATA];
__device__ float g_kern[SUB_NO][2][T_NO];
__device__ __align__(16) float g_B[64][KSLOTS];  // padding rows/slots stay 0

#define PREP_BLOCKS 313              // 313*8 warps >= 2500 columns

// ------------------------------------------------- fused prep: columns (warp each) + kern table
__global__ void prep_all(const float* __restrict__ u, const float* __restrict__ v,
                         const float* __restrict__ clog, float* __restrict__ out,
                         const float* __restrict__ W_syn, const float* __restrict__ Tau,
                         const float* __restrict__ Delta) {
    if (blockIdx.x >= PREP_BLOCKS) {
        int i = (blockIdx.x - PREP_BLOCKS) * 256 + threadIdx.x;
        if (i < SUB_NO * 2 * T_NO) {
            int tau = i % T_NO;
            int j = (i / T_NO) % 2;
            int s = i / (2 * T_NO);
            float d  = expf(Delta[s * 2 + j]);
            float tt = fmaxf((float)tau - d, 0.f) / expf(Tau[s * 2 + j]);
            g_kern[s][j][tau] = tt * expf(-tt) * W_syn[s * 2 + j];
        }
        return;
    }
    const unsigned FULL = 0xFFFFFFFFu;
    int n = (blockIdx.x * blockDim.x + threadIdx.x) >> 5;
    int lane = threadIdx.x & 31;
    if (n >= NSYN) return;
    const bool act = lane < SUB_NO;

    float cl = act ? clog[lane * NSYN + n] : -1e30f;
    float m = cl;
#pragma unroll
    for (int o = 16; o; o >>= 1) m = fmaxf(m, __shfl_xor_sync(FULL, m, o));
    float e = act ? expf(cl - m) : 0.f;
    float sum = e;
#pragma unroll
    for (int o = 16; o; o >>= 1) sum += __shfl_xor_sync(FULL, sum, o);
    float th = e / sum;

    float rz = -1e30f;
    if (act) {
        float us = u[lane * NSYN + n];
        rz = logf(th) - logf(-logf(us));
    }
    float mr = rz;
#pragma unroll
    for (int o = 16; o; o >>= 1) mr = fmaxf(mr, __shfl_xor_sync(FULL, mr, o));
    unsigned msk = __ballot_sync(FULL, rz == mr);
    int k = __ffs(msk) - 1;

    float vs = act ? v[lane * NSYN + n] : 0.5f;
    float lv = logf(vs);
    float lvk = __shfl_sync(FULL, lv, k);

    if (act) {
        float hard = (lane == k) ? 1.f : 0.f;
        float z_same = -logf(-lv);
        float z_diff = -logf((-lv) / th - lvk);
        float zb = (lane == k) ? z_same : z_diff;
        float sz  = 1.f / (1.f + expf(-2.f * rz)) + 1e-9f;
        float szb = 1.f / (1.f + expf(-2.f * zb)) + 1e-9f;
        out[OFF_THETA + lane * NSYN + n] = th;
        out[OFF_HARD  + lane * NSYN + n] = hard;
        out[OFF_SOFT  + lane * NSYN + n] = sz;
        out[OFF_ZB    + lane * NSYN + n] = szb;
        int slot = (n < E_NO) ? n : (NCHUNK_E * 32 + (n - E_NO));
        g_B[lane     ][slot] = hard;
        g_B[20 + lane][slot] = sz;
        g_B[40 + lane][slot] = szb;
    }
}

// ------------------------------------------------- helpers
__device__ __forceinline__ uint32_t smem_u32(const void* p) {
    uint32_t r;
    asm("{ .reg .u64 t; cvta.to.shared.u64 t, %1; cvt.u32.u64 %0, t; }" : "=r"(r) : "l"(p));
    return r;
}
__device__ __forceinline__ void ldsm4(uint32_t r[4], uint32_t addr) {
    asm volatile("ldmatrix.sync.aligned.m8n8.x4.shared.b16 {%0,%1,%2,%3}, [%4];"
                 : "=r"(r[0]), "=r"(r[1]), "=r"(r[2]), "=r"(r[3]) : "r"(addr));
}
__device__ __forceinline__ void cpa16(uint32_t dst, const void* src, int sz) {
    asm volatile("cp.async.cg.shared.global [%0], [%1], 16, %2;"
                 :: "r"(dst), "l"(src), "r"(sz));
}
__device__ __forceinline__ void hmma_tf32(float* a, uint32_t a0, uint32_t a1, uint32_t a2,
                                          uint32_t a3, uint32_t b0, uint32_t b1) {
    asm volatile(
        "mma.sync.aligned.m16n8k8.row.col.f32.tf32.tf32.f32 "
        "{%0,%1,%2,%3}, {%4,%5,%6,%7}, {%8,%9}, {%0,%1,%2,%3};"
        : "+f"(a[0]), "+f"(a[1]), "+f"(a[2]), "+f"(a[3])
        : "r"(a0), "r"(a1), "r"(a2), "r"(a3), "r"(b0), "r"(b1));
}

// ------------------------------------------------- tf32 mma.sync GEMM
// grid 139 (no tail wave), 256 threads, M-tile 144 rows, 7-stage cp.async ring (depth-6).
// Warp w: m-tile w (nt 0..7) + m-tile 8 (nt = w). E chunks -> g_in[0], I -> g_in[1].
#define APAD    36
#define MROWS   144
#define STAGES  7
#define A_STAGE (MROWS * APAD)       // floats
#define B_STAGE (64 * APAD)
#define GEMM_SMEM (STAGES * (A_STAGE + B_STAGE) * 4)

__global__ void __launch_bounds__(256)
gemm_mma(const float* __restrict__ Se, const float* __restrict__ Si) {
    extern __shared__ float smem[];
    float* Asm = smem;
    float* Bsm = smem + STAGES * A_STAGE;

    const int tid  = threadIdx.x;
    const int lane = tid & 31;
    const int wid  = tid >> 5;
    const int g    = lane >> 2;
    const int tg   = lane & 3;
    const int tBase = blockIdx.x * MROWS;

    const uint32_t aBase = smem_u32(Asm);
    const uint32_t bBase = smem_u32(Bsm);

    // ldmatrix addresses (stage 0): main m-tile (rows 16*wid+) and tail tile (rows 128+)
    const int lrow = (lane & 7) + ((lane >> 3) & 1) * 8;
    const int lcol = (lane >> 4) * 4;
    const uint32_t aAddrM = aBase + (uint32_t)((wid * 16 + lrow) * APAD + lcol) * 4;
    const uint32_t aAddrT = aBase + (uint32_t)((128 + lrow) * APAD + lcol) * 4;
    uint32_t bAddr[4];
#pragma unroll
    for (int p = 0; p < 4; p++) {
        int bRow = (2 * p + (lane >> 4)) * 8 + (lane & 7);
        int bCol = ((lane >> 3) & 1) * 4;
        bAddr[p] = bBase + (uint32_t)(bRow * APAD + bCol) * 4;
    }

    const int sr = tid >> 3;          // 0..31
    const int sc = (tid & 7) * 4;     // 0..28

    float acc[8][4], accT[4];
#pragma unroll
    for (int nt = 0; nt < 8; nt++)
#pragma unroll
        for (int q = 0; q < 4; q++) acc[nt][q] = 0.f;
#pragma unroll
    for (int q = 0; q < 4; q++) accT[q] = 0.f;

    auto issue = [&](int c, int st) {
        const float* S; int ld, kmax, j0;
        if (c < NCHUNK_E) { S = Se; ld = E_NO; kmax = E_NO; j0 = c * 32; }
        else              { S = Si; ld = I_NO; kmax = I_NO; j0 = (c - NCHUNK_E) * 32; }
        int j = j0 + sc;
        bool jok = j < kmax;
        uint32_t adst = aBase + (uint32_t)(st * A_STAGE + sr * APAD + sc) * 4;
#pragma unroll
        for (int it = 0; it < 5; it++) {
            int row = sr + it * 32;
            if (it == 4 && sr >= 16) break;       // rows 128..143 only
            int t = tBase + row;
            bool ok = jok && (t < T_DATA);
            cpa16(adst + it * 32 * APAD * 4,
                  ok ? (const void*)(S + (size_t)t * ld + j) : (const void*)S,
                  ok ? 16 : 0);
        }
        uint32_t bdst = bBase + (uint32_t)(st * B_STAGE + sr * APAD + sc) * 4;
        int slot = c * 32 + sc;
#pragma unroll
        for (int it = 0; it < 2; it++)
            cpa16(bdst + it * 32 * APAD * 4, &g_B[sr + it * 32][slot], 16);
    };

    auto compute = [&](int st) {
        const uint32_t ao = (uint32_t)(st * A_STAGE) * 4;
        const uint32_t bo = (uint32_t)(st * B_STAGE) * 4;
#pragma unroll
        for (int k8 = 0; k8 < 4; k8++) {
            const uint32_t koff = k8 * 32;
            uint32_t afm[4], aft[4], bf[4][4];
            ldsm4(afm, aAddrM + ao + koff);
            ldsm4(aft, aAddrT + ao + koff);
#pragma unroll
            for (int p = 0; p < 4; p++) ldsm4(bf[p], bAddr[p] + bo + koff);
#pragma unroll
            for (int nt = 0; nt < 8; nt++)
                hmma_tf32(acc[nt], afm[0], afm[1], afm[2], afm[3],
                          bf[nt >> 1][(nt & 1) * 2], bf[nt >> 1][(nt & 1) * 2 + 1]);
            hmma_tf32(accT, aft[0], aft[1], aft[2], aft[3],
                      bf[wid >> 1][(wid & 1) * 2], bf[wid >> 1][(wid & 1) * 2 + 1]);
        }
    };

    auto store_acc = [&](int dst) {
        int t0 = tBase + wid * 16 + g;
#pragma unroll
        for (int nt = 0; nt < 8; nt++) {
            int o0 = nt * 8 + tg * 2;
            if (o0 < 60) {
                if (t0 < T_DATA) {
                    g_in[dst][o0    ][t0] = acc[nt][0];
                    g_in[dst][o0 + 1][t0] = acc[nt][1];
                }
                if (t0 + 8 < T_DATA) {
                    g_in[dst][o0    ][t0 + 8] = acc[nt][2];
                    g_in[dst][o0 + 1][t0 + 8] = acc[nt][3];
                }
            }
        }
        int tT = tBase + 128 + g;
        int oT = wid * 8 + tg * 2;
        if (oT < 60) {
            if (tT < T_DATA) {
                g_in[dst][oT    ][tT] = accT[0];
                g_in[dst][oT + 1][tT] = accT[1];
            }
            if (tT + 8 < T_DATA) {
                g_in[dst][oT    ][tT + 8] = accT[2];
                g_in[dst][oT + 1][tT + 8] = accT[3];
            }
        }
    };

    // prefetch depth-6
#pragma unroll
    for (int p = 0; p < STAGES - 1; p++) {
        issue(p, p);
        asm volatile("cp.async.commit_group;" ::: "memory");
    }

    int st = 0;
    for (int c = 0; c < NCHUNKS; c++) {
        asm volatile("cp.async.wait_group %0;" :: "n"(STAGES - 2) : "memory");
        __syncthreads();
        int nc = c + STAGES - 1;
        int nst = nc % STAGES;
        if (nc < NCHUNKS) issue(nc, nst);
        asm volatile("cp.async.commit_group;" ::: "memory");
        compute(st);
        if (++st == STAGES) st = 0;
        if (c == NCHUNK_E - 1) {
            store_acc(0);
#pragma unroll
            for (int nt = 0; nt < 8; nt++)
#pragma unroll
                for (int q = 0; q < 4; q++) acc[nt][q] = 0.f;
#pragma unroll
            for (int q = 0; q < 4; q++) accT[q] = 0.f;
        }
    }
    store_acc(1);
}

// ------------------------------------------------- causal FIR: float4 sliding window
__global__ void conv_kernel(const float* __restrict__ Tau, const float* __restrict__ Delta) {
    const int o = blockIdx.y;
    const int s = o % 20;
    const int tBase = blockIdx.x * CTT;
    const int tid = threadIdx.x;

    float de = expf(Delta[s * 2 + 0]), di = expf(Delta[s * 2 + 1]);
    float te = expf(Tau[s * 2 + 0]),   ti = expf(Tau[s * 2 + 1]);
    int L = (int)(fmaxf(de + 27.f * te, di + 27.f * ti)) + 2;
    if (L > T_NO) L = T_NO;
    const int L4 = (L + 3) & ~3;

    __shared__ __align__(16) float we[CTT + OFFS], wi[CTT + OFFS];
    __shared__ __align__(16) float ke[204], ki[204];

    for (int i = tid; i < CTT + OFFS; i += 128) {
        int gt = tBase - OFFS + i;
        bool ok = (gt >= 0) && (gt < T_DATA);
        we[i] = ok ? g_in[0][o][gt] : 0.f;
        wi[i] = ok ? g_in[1][o][gt] : 0.f;
    }
    for (int i = tid; i < 204; i += 128) {
        ke[i] = (i < T_NO) ? g_kern[s][0][i] : 0.f;
        ki[i] = (i < T_NO) ? g_kern[s][1][i] : 0.f;
    }
    __syncthreads();

    const int t0 = tid * 4;
    float a0 = 0.f, a1 = 0.f, a2 = 0.f, a3 = 0.f;

    float4 lo_e = *(const float4*)&we[OFFS + t0 - 4];
    float4 hi_e = *(const float4*)&we[OFFS + t0];
    float4 lo_i = *(const float4*)&wi[OFFS + t0 - 4];
    float4 hi_i = *(const float4*)&wi[OFFS + t0];

    for (int tau4 = 0; tau4 < L4; tau4 += 4) {
        float4 kfe = *(const float4*)&ke[tau4];
        float4 kfi = *(const float4*)&ki[tau4];
        a0 = fmaf(hi_e.x, kfe.x, fmaf(hi_i.x, kfi.x, a0));
        a1 = fmaf(hi_e.y, kfe.x, fmaf(hi_i.y, kfi.x, a1));
        a2 = fmaf(hi_e.z, kfe.x, fmaf(hi_i.z, kfi.x, a2));
        a3 = fmaf(hi_e.w, kfe.x, fmaf(hi_i.w, kfi.x, a3));
        a0 = fmaf(lo_e.w, kfe.y, fmaf(lo_i.w, kfi.y, a0));
        a1 = fmaf(hi_e.x, kfe.y, fmaf(hi_i.x, kfi.y, a1));
        a2 = fmaf(hi_e.y, kfe.y, fmaf(hi_i.y, kfi.y, a2));
        a3 = fmaf(hi_e.z, kfe.y, fmaf(hi_i.z, kfi.y, a3));
        a0 = fmaf(lo_e.z, kfe.z, fmaf(lo_i.z, kfi.z, a0));
        a1 = fmaf(lo_e.w, kfe.z, fmaf(lo_i.w, kfi.z, a1));
        a2 = fmaf(hi_e.x, kfe.z, fmaf(hi_i.x, kfi.z, a2));
        a3 = fmaf(hi_e.y, kfe.z, fmaf(hi_i.y, kfi.z, a3));
        a0 = fmaf(lo_e.y, kfe.w, fmaf(lo_i.y, kfi.w, a0));
        a1 = fmaf(lo_e.z, kfe.w, fmaf(lo_i.z, kfi.w, a1));
        a2 = fmaf(lo_e.w, kfe.w, fmaf(lo_i.w, kfi.w, a2));
        a3 = fmaf(hi_e.x, kfe.w, fmaf(hi_i.x, kfi.w, a3));
        hi_e = lo_e; hi_i = lo_i;
        lo_e = *(const float4*)&we[OFFS + t0 - tau4 - 8];
        lo_i = *(const float4*)&wi[OFFS + t0 - tau4 - 8];
    }

    int t = tBase + t0;
    if (t     < T_DATA) g_syn[o][t]     = a0;
    if (t + 1 < T_DATA) g_syn[o][t + 1] = a1;
    if (t + 2 < T_DATA) g_syn[o][t + 2] = a2;
    if (t + 3 < T_DATA) g_syn[o][t + 3] = a3;
}

// ------------------------------------------------- dendritic tree + tanh
__global__ void tree_kernel(const float* __restrict__ W_sub, const float* __restrict__ V_o,
                            float* __restrict__ outp) {
    int t = blockIdx.x * blockDim.x + threadIdx.x;
    int var = blockIdx.y;
    if (t >= T_DATA) return;

    float ws[SUB_NO];
#pragma unroll
    for (int s = 0; s < SUB_NO; s++) ws[s] = W_sub[s];

    float so[SUB_NO];
#pragma unroll
    for (int si = SUB_NO - 1; si >= 0; si--) {
        float x = g_syn[var * 20 + si][t];
        float leaf = 0.f;
        if (2 * si + 1 < SUB_NO) leaf += so[2 * si + 1] * ws[2 * si + 1];
        if (2 * si + 2 < SUB_NO) leaf += so[2 * si + 2] * ws[2 * si + 2];
        so[si] = tanhf(x + leaf);
    }
    outp[var * T_DATA + t] = so[0] * ws[0] + V_o[0];
}

// ----------------------------------------------------------------------------
extern "C" void kernel_launch(void* const* d_in, const int* in_sizes, int n_in,
                              void* d_out, int out_size) {
    const float* Se    = (const float*)d_in[0];
    const float* Si    = (const float*)d_in[1];
    const float* u     = (const float*)d_in[2];
    const float* v     = (const float*)d_in[3];
    const float* Wsyn  = (const float*)d_in[4];
    const float* Tau   = (const float*)d_in[5];
    const float* Delta = (const float*)d_in[6];
    const float* Wsub  = (const float*)d_in[7];
    const float* Vo    = (const float*)d_in[8];
    const float* Clog  = (const float*)d_in[10];
    float* out = (float*)d_out;

    cudaFuncSetAttribute(gemm_mma, cudaFuncAttributeMaxDynamicSharedMemorySize, GEMM_SMEM);

    int prep_grid = PREP_BLOCKS + (SUB_NO * 2 * T_NO + 255) / 256;
    prep_all<<<prep_grid, 256>>>(u, v, Clog, out, Wsyn, Tau, Delta);
    gemm_mma<<<(T_DATA + MROWS - 1) / MROWS, 256, GEMM_SMEM>>>(Se, Si);
    conv_kernel<<<dim3((T_DATA + CTT - 1) / CTT, NCH), 128>>>(Tau, Delta);
    tree_kernel<<<dim3((T_DATA + 255) / 256, 3), 256>>>(Wsub, Vo, out);
}

// round 15
// speedup vs baseline: 1.0274x; 1.0274x over previous
#include <cuda_runtime.h>
#include <math.h>
#include <stdint.h>

#define SUB_NO 20
#define T_NO   201
#define E_NO   2000
#define I_NO   500
#define NSYN   2500
#define T_DATA 20000
#define NCH    60
#define CTT    512
#define OFFS   208

#define NCHUNK_E 63
#define NCHUNK_I 16
#define NCHUNKS  (NCHUNK_E + NCHUNK_I)
#define KSLOTS   (NCHUNKS * 32)     // 2528

// output layout (floats)
#define OFF_THETA 60000
#define OFF_HARD  110000
#define OFF_SOFT  160000
#define OFF_ZB    210000

// scratch
__device__ float g_in[2][NCH][T_DATA];
__device__ float g_syn[NCH][T_DATA];
__device__ float g_kern[SUB_NO][2][T_NO];
__device__ __align__(16) float g_B[64][KSLOTS];  // padding rows/slots stay 0

#define PREP_BLOCKS 313              // 313*8 warps >= 2500 columns

// ------------------------------------------------- fused prep: columns (warp each) + kern table
__global__ void prep_all(const float* __restrict__ u, const float* __restrict__ v,
                         const float* __restrict__ clog, float* __restrict__ out,
                         const float* __restrict__ W_syn, const float* __restrict__ Tau,
                         const float* __restrict__ Delta) {
    if (blockIdx.x >= PREP_BLOCKS) {
        int i = (blockIdx.x - PREP_BLOCKS) * 256 + threadIdx.x;
        if (i < SUB_NO * 2 * T_NO) {
            int tau = i % T_NO;
            int j = (i / T_NO) % 2;
            int s = i / (2 * T_NO);
            float d  = expf(Delta[s * 2 + j]);
            float tt = fmaxf((float)tau - d, 0.f) / expf(Tau[s * 2 + j]);
            g_kern[s][j][tau] = tt * expf(-tt) * W_syn[s * 2 + j];
        }
        return;
    }
    const unsigned FULL = 0xFFFFFFFFu;
    int n = (blockIdx.x * blockDim.x + threadIdx.x) >> 5;
    int lane = threadIdx.x & 31;
    if (n >= NSYN) return;
    const bool act = lane < SUB_NO;

    float cl = act ? clog[lane * NSYN + n] : -1e30f;
    float m = cl;
#pragma unroll
    for (int o = 16; o; o >>= 1) m = fmaxf(m, __shfl_xor_sync(FULL, m, o));
    float e = act ? expf(cl - m) : 0.f;
    float sum = e;
#pragma unroll
    for (int o = 16; o; o >>= 1) sum += __shfl_xor_sync(FULL, sum, o);
    float th = e / sum;

    float rz = -1e30f;
    if (act) {
        float us = u[lane * NSYN + n];
        rz = logf(th) - logf(-logf(us));
    }
    float mr = rz;
#pragma unroll
    for (int o = 16; o; o >>= 1) mr = fmaxf(mr, __shfl_xor_sync(FULL, mr, o));
    unsigned msk = __ballot_sync(FULL, rz == mr);
    int k = __ffs(msk) - 1;

    float vs = act ? v[lane * NSYN + n] : 0.5f;
    float lv = logf(vs);
    float lvk = __shfl_sync(FULL, lv, k);

    if (act) {
        float hard = (lane == k) ? 1.f : 0.f;
        float z_same = -logf(-lv);
        float z_diff = -logf((-lv) / th - lvk);
        float zb = (lane == k) ? z_same : z_diff;
        float sz  = 1.f / (1.f + expf(-2.f * rz)) + 1e-9f;
        float szb = 1.f / (1.f + expf(-2.f * zb)) + 1e-9f;
        out[OFF_THETA + lane * NSYN + n] = th;
        out[OFF_HARD  + lane * NSYN + n] = hard;
        out[OFF_SOFT  + lane * NSYN + n] = sz;
        out[OFF_ZB    + lane * NSYN + n] = szb;
        int slot = (n < E_NO) ? n : (NCHUNK_E * 32 + (n - E_NO));
        g_B[lane     ][slot] = hard;
        g_B[20 + lane][slot] = sz;
        g_B[40 + lane][slot] = szb;
    }
}

// ------------------------------------------------- helpers
__device__ __forceinline__ uint32_t smem_u32(const void* p) {
    uint32_t r;
    asm("{ .reg .u64 t; cvta.to.shared.u64 t, %1; cvt.u32.u64 %0, t; }" : "=r"(r) : "l"(p));
    return r;
}
__device__ __forceinline__ void ldsm4(uint32_t r[4], uint32_t addr) {
    asm volatile("ldmatrix.sync.aligned.m8n8.x4.shared.b16 {%0,%1,%2,%3}, [%4];"
                 : "=r"(r[0]), "=r"(r[1]), "=r"(r[2]), "=r"(r[3]) : "r"(addr));
}
__device__ __forceinline__ void cpa16(uint32_t dst, const void* src, int sz) {
    asm volatile("cp.async.cg.shared.global [%0], [%1], 16, %2;"
                 :: "r"(dst), "l"(src), "r"(sz));
}
__device__ __forceinline__ void hmma_tf32(float* a, uint32_t a0, uint32_t a1, uint32_t a2,
                                          uint32_t a3, uint32_t b0, uint32_t b1) {
    asm volatile(
        "mma.sync.aligned.m16n8k8.row.col.f32.tf32.tf32.f32 "
        "{%0,%1,%2,%3}, {%4,%5,%6,%7}, {%8,%9}, {%0,%1,%2,%3};"
        : "+f"(a[0]), "+f"(a[1]), "+f"(a[2]), "+f"(a[3])
        : "r"(a0), "r"(a1), "r"(a2), "r"(a3), "r"(b0), "r"(b1));
}

// ------------------------------------------------- tf32 mma.sync GEMM, cp.async 2-stage
// M-tile 64 rows -> grid 313, 128 threads (4 warps), 36.9KB smem -> up to 4 CTAs/SM
// resident (true multi-CTA overlap; single wave since conc >= 592).
// Warp w owns t-rows [tBase+16w, +16). E chunks -> g_in[0], I chunks -> g_in[1].
#define APAD   36
#define MROWS  64
#define STAGES 2
#define A_STAGE (MROWS * APAD)      // floats
#define B_STAGE (64 * APAD)
#define GEMM_SMEM (STAGES * (A_STAGE + B_STAGE) * 4)

__global__ void __launch_bounds__(128, 4)
gemm_mma(const float* __restrict__ Se, const float* __restrict__ Si) {
    extern __shared__ float smem[];
    float* Asm = smem;
    float* Bsm = smem + STAGES * A_STAGE;

    const int tid  = threadIdx.x;
    const int lane = tid & 31;
    const int wid  = tid >> 5;          // 0..3
    const int g    = lane >> 2;
    const int tg   = lane & 3;
    const int tBase = blockIdx.x * MROWS;

    const uint32_t aBase = smem_u32(Asm);
    const uint32_t bBase = smem_u32(Bsm);

    // ldmatrix lane->address (stage 0)
    const int aRow = wid * 16 + (lane & 7) + ((lane >> 3) & 1) * 8;
    const int aCol = (lane >> 4) * 4;
    const uint32_t aAddr = aBase + (uint32_t)(aRow * APAD + aCol) * 4;
    uint32_t bAddr[4];
#pragma unroll
    for (int p = 0; p < 4; p++) {
        int bRow = (2 * p + (lane >> 4)) * 8 + (lane & 7);
        int bCol = ((lane >> 3) & 1) * 4;
        bAddr[p] = bBase + (uint32_t)(bRow * APAD + bCol) * 4;
    }

    // staging indices: 128 threads -> (row 0..15, 4-float col)
    const int sr = tid >> 3;          // 0..15
    const int sc = (tid & 7) * 4;     // 0..28

    float acc[8][4];
#pragma unroll
    for (int nt = 0; nt < 8; nt++)
#pragma unroll
        for (int q = 0; q < 4; q++) acc[nt][q] = 0.f;

    auto issue = [&](int c, int st) {
        const float* S; int ld, kmax, j0;
        if (c < NCHUNK_E) { S = Se; ld = E_NO; kmax = E_NO; j0 = c * 32; }
        else              { S = Si; ld = I_NO; kmax = I_NO; j0 = (c - NCHUNK_E) * 32; }
        int j = j0 + sc;
        bool jok = j < kmax;
        uint32_t adst = aBase + (uint32_t)(st * A_STAGE + sr * APAD + sc) * 4;
#pragma unroll
        for (int it = 0; it < 4; it++) {           // 4 x 16 = 64 rows
            int t = tBase + sr + it * 16;
            bool ok = jok && (t < T_DATA);
            cpa16(adst + it * 16 * APAD * 4,
                  ok ? (const void*)(S + (size_t)t * ld + j) : (const void*)S,
                  ok ? 16 : 0);
        }
        uint32_t bdst = bBase + (uint32_t)(st * B_STAGE + sr * APAD + sc) * 4;
        int slot = c * 32 + sc;
#pragma unroll
        for (int it = 0; it < 4; it++)             // 4 x 16 = 64 rows
            cpa16(bdst + it * 16 * APAD * 4, &g_B[sr + it * 16][slot], 16);
    };

    auto compute = [&](int st) {
        const uint32_t ao = (uint32_t)(st * A_STAGE) * 4;
        const uint32_t bo = (uint32_t)(st * B_STAGE) * 4;
#pragma unroll
        for (int k8 = 0; k8 < 4; k8++) {
            const uint32_t koff = k8 * 32;
            uint32_t af[4], bf[4][4];
            ldsm4(af, aAddr + ao + koff);
#pragma unroll
            for (int p = 0; p < 4; p++) ldsm4(bf[p], bAddr[p] + bo + koff);
#pragma unroll
            for (int nt = 0; nt < 8; nt++)
                hmma_tf32(acc[nt], af[0], af[1], af[2], af[3],
                          bf[nt >> 1][(nt & 1) * 2], bf[nt >> 1][(nt & 1) * 2 + 1]);
        }
    };

    auto store_acc = [&](int dst) {
        int t0 = tBase + wid * 16 + g;
#pragma unroll
        for (int nt = 0; nt < 8; nt++) {
            int o0 = nt * 8 + tg * 2;
            if (o0 < 60) {
                if (t0 < T_DATA) {
                    g_in[dst][o0    ][t0] = acc[nt][0];
                    g_in[dst][o0 + 1][t0] = acc[nt][1];
                }
                if (t0 + 8 < T_DATA) {
                    g_in[dst][o0    ][t0 + 8] = acc[nt][2];
                    g_in[dst][o0 + 1][t0 + 8] = acc[nt][3];
                }
            }
        }
    };

    // prefetch chunk 0 (depth-1 lookahead, same pattern as the passing R11 kernel)
    issue(0, 0);
    asm volatile("cp.async.commit_group;" ::: "memory");

    for (int c = 0; c < NCHUNKS; c++) {
        asm volatile("cp.async.wait_group 0;" ::: "memory");
        __syncthreads();
        if (c + 1 < NCHUNKS) {
            issue(c + 1, (c + 1) & 1);
            asm volatile("cp.async.commit_group;" ::: "memory");
        }
        compute(c & 1);
        if (c == NCHUNK_E - 1) {
            store_acc(0);
#pragma unroll
            for (int nt = 0; nt < 8; nt++)
#pragma unroll
                for (int q = 0; q < 4; q++) acc[nt][q] = 0.f;
        }
    }
    store_acc(1);
}

// ------------------------------------------------- causal FIR: float4 sliding window
__global__ void conv_kernel(const float* __restrict__ Tau, const float* __restrict__ Delta) {
    const int o = blockIdx.y;
    const int s = o % 20;
    const int tBase = blockIdx.x * CTT;
    const int tid = threadIdx.x;

    float de = expf(Delta[s * 2 + 0]), di = expf(Delta[s * 2 + 1]);
    float te = expf(Tau[s * 2 + 0]),   ti = expf(Tau[s * 2 + 1]);
    int L = (int)(fmaxf(de + 27.f * te, di + 27.f * ti)) + 2;
    if (L > T_NO) L = T_NO;
    const int L4 = (L + 3) & ~3;

    __shared__ __align__(16) float we[CTT + OFFS], wi[CTT + OFFS];
    __shared__ __align__(16) float ke[204], ki[204];

    for (int i = tid; i < CTT + OFFS; i += 128) {
        int gt = tBase - OFFS + i;
        bool ok = (gt >= 0) && (gt < T_DATA);
        we[i] = ok ? g_in[0][o][gt] : 0.f;
        wi[i] = ok ? g_in[1][o][gt] : 0.f;
    }
    for (int i = tid; i < 204; i += 128) {
        ke[i] = (i < T_NO) ? g_kern[s][0][i] : 0.f;
        ki[i] = (i < T_NO) ? g_kern[s][1][i] : 0.f;
    }
    __syncthreads();

    const int t0 = tid * 4;
    float a0 = 0.f, a1 = 0.f, a2 = 0.f, a3 = 0.f;

    float4 lo_e = *(const float4*)&we[OFFS + t0 - 4];
    float4 hi_e = *(const float4*)&we[OFFS + t0];
    float4 lo_i = *(const float4*)&wi[OFFS + t0 - 4];
    float4 hi_i = *(const float4*)&wi[OFFS + t0];

    for (int tau4 = 0; tau4 < L4; tau4 += 4) {
        float4 kfe = *(const float4*)&ke[tau4];
        float4 kfi = *(const float4*)&ki[tau4];
        a0 = fmaf(hi_e.x, kfe.x, fmaf(hi_i.x, kfi.x, a0));
        a1 = fmaf(hi_e.y, kfe.x, fmaf(hi_i.y, kfi.x, a1));
        a2 = fmaf(hi_e.z, kfe.x, fmaf(hi_i.z, kfi.x, a2));
        a3 = fmaf(hi_e.w, kfe.x, fmaf(hi_i.w, kfi.x, a3));
        a0 = fmaf(lo_e.w, kfe.y, fmaf(lo_i.w, kfi.y, a0));
        a1 = fmaf(hi_e.x, kfe.y, fmaf(hi_i.x, kfi.y, a1));
        a2 = fmaf(hi_e.y, kfe.y, fmaf(hi_i.y, kfi.y, a2));
        a3 = fmaf(hi_e.z, kfe.y, fmaf(hi_i.z, kfi.y, a3));
        a0 = fmaf(lo_e.z, kfe.z, fmaf(lo_i.z, kfi.z, a0));
        a1 = fmaf(lo_e.w, kfe.z, fmaf(lo_i.w, kfi.z, a1));
        a2 = fmaf(hi_e.x, kfe.z, fmaf(hi_i.x, kfi.z, a2));
        a3 = fmaf(hi_e.y, kfe.z, fmaf(hi_i.y, kfi.z, a3));
        a0 = fmaf(lo_e.y, kfe.w, fmaf(lo_i.y, kfi.w, a0));
        a1 = fmaf(lo_e.z, kfe.w, fmaf(lo_i.z, kfi.w, a1));
        a2 = fmaf(lo_e.w, kfe.w, fmaf(lo_i.w, kfi.w, a2));
        a3 = fmaf(hi_e.x, kfe.w, fmaf(hi_i.x, kfi.w, a3));
        hi_e = lo_e; hi_i = lo_i;
        lo_e = *(const float4*)&we[OFFS + t0 - tau4 - 8];
        lo_i = *(const float4*)&wi[OFFS + t0 - tau4 - 8];
    }

    int t = tBase + t0;
    if (t     < T_DATA) g_syn[o][t]     = a0;
    if (t + 1 < T_DATA) g_syn[o][t + 1] = a1;
    if (t + 2 < T_DATA) g_syn[o][t + 2] = a2;
    if (t + 3 < T_DATA) g_syn[o][t + 3] = a3;
}

// ------------------------------------------------- dendritic tree + tanh
__global__ void tree_kernel(const float* __restrict__ W_sub, const float* __restrict__ V_o,
                            float* __restrict__ outp) {
    int t = blockIdx.x * blockDim.x + threadIdx.x;
    int var = blockIdx.y;
    if (t >= T_DATA) return;

    float ws[SUB_NO];
#pragma unroll
    for (int s = 0; s < SUB_NO; s++) ws[s] = W_sub[s];

    float so[SUB_NO];
#pragma unroll
    for (int si = SUB_NO - 1; si >= 0; si--) {
        float x = g_syn[var * 20 + si][t];
        float leaf = 0.f;
        if (2 * si + 1 < SUB_NO) leaf += so[2 * si + 1] * ws[2 * si + 1];
        if (2 * si + 2 < SUB_NO) leaf += so[2 * si + 2] * ws[2 * si + 2];
        so[si] = tanhf(x + leaf);
    }
    outp[var * T_DATA + t] = so[0] * ws[0] + V_o[0];
}

// ----------------------------------------------------------------------------
extern "C" void kernel_launch(void* const* d_in, const int* in_sizes, int n_in,
                              void* d_out, int out_size) {
    const float* Se    = (const float*)d_in[0];
    const float* Si    = (const float*)d_in[1];
    const float* u     = (const float*)d_in[2];
    const float* v     = (const float*)d_in[3];
    const float* Wsyn  = (const float*)d_in[4];
    const float* Tau   = (const float*)d_in[5];
    const float* Delta = (const float*)d_in[6];
    const float* Wsub  = (const float*)d_in[7];
    const float* Vo    = (const float*)d_in[8];
    const float* Clog  = (const float*)d_in[10];
    float* out = (float*)d_out;

    cudaFuncSetAttribute(gemm_mma, cudaFuncAttributeMaxDynamicSharedMemorySize, GEMM_SMEM);

    int prep_grid = PREP_BLOCKS + (SUB_NO * 2 * T_NO + 255) / 256;
    prep_all<<<prep_grid, 256>>>(u, v, Clog, out, Wsyn, Tau, Delta);
    gemm_mma<<<(T_DATA + MROWS - 1) / MROWS, 128, GEMM_SMEM>>>(Se, Si);
    conv_kernel<<<dim3((T_DATA + CTT - 1) / CTT, NCH), 128>>>(Tau, Delta);
    tree_kernel<<<dim3((T_DATA + 255) / 256, 3), 256>>>(Wsub, Vo, out);
}